// round 1
// baseline (speedup 1.0000x reference)
#include <cuda_runtime.h>
#include <math.h>

// ---------------- problem constants ----------------
#define TT     16384            // tokens = B*S
#define DD     1024             // n_embd
#define EE     8                // experts
#define DFF    2048             // per-expert ffn width
#define NN     32768            // N = T*K
#define RBLOCKS 128             // router grid blocks
#define MAX_TILES 264           // >= sum_e ceil(cnt_e/128) worst case (263)
#define MAX_ROWS (MAX_TILES*128)
#define OUT_OFF ((size_t)TT*DD) // where z_loss/lb_loss/f_i go in d_out

// ---------------- device scratch (no allocs allowed) ----------------
__device__ int   g_counts[EE];
__device__ int   g_cursor[EE];
__device__ int   g_offpad[EE];
__device__ int   g_tile_expert[MAX_TILES];
__device__ int   g_sel[NN];
__device__ float g_rw[NN];
__device__ int   g_list[MAX_ROWS];
__device__ float g_partials[RBLOCKS][9];
__device__ float g_H[(size_t)MAX_ROWS * DFF];   // post-gelu hidden, padded layout
__device__ float g_O[(size_t)NN * DD];          // per-(token,k) weighted output rows

// ---------------- init: reset counters, invalidate list ----------------
__global__ void moe_init_kernel() {
    int i = blockIdx.x * 256 + threadIdx.x;
    if (i < EE) g_counts[i] = 0;
    if (i < MAX_ROWS) g_list[i] = -1;
}

// ---------------- router: logits, softmax, top-2, loss partials ----------------
// grid = RBLOCKS blocks x 256 threads; warp-per-token, 16 tokens/warp.
__global__ __launch_bounds__(256) void moe_router_kernel(
    const float* __restrict__ x, const float* __restrict__ router_w)
{
    __shared__ float rw_s[EE * DD];       // 32 KB
    __shared__ float warp_part[8][9];
    for (int i = threadIdx.x; i < EE * DD; i += 256) rw_s[i] = router_w[i];
    __syncthreads();

    int warp = threadIdx.x >> 5, lane = threadIdx.x & 31;
    int wg = blockIdx.x * 8 + warp;       // global warp id: 0..1023
    float zp = 0.f;
    float pp[EE];
    #pragma unroll
    for (int e = 0; e < EE; e++) pp[e] = 0.f;

    for (int t = wg; t < TT; t += RBLOCKS * 8) {
        const float* xr = x + (size_t)t * DD;
        float xv[32];
        #pragma unroll
        for (int i = 0; i < 32; i++) xv[i] = xr[lane + 32 * i];

        float logit[EE];
        #pragma unroll
        for (int e = 0; e < EE; e++) {
            float s = 0.f;
            #pragma unroll
            for (int i = 0; i < 32; i++) s = fmaf(xv[i], rw_s[e * DD + lane + 32 * i], s);
            #pragma unroll
            for (int o = 16; o > 0; o >>= 1) s += __shfl_xor_sync(0xFFFFFFFFu, s, o);
            logit[e] = s;
        }
        if (lane == 0) {
            float m = logit[0];
            #pragma unroll
            for (int e = 1; e < EE; e++) m = fmaxf(m, logit[e]);
            float se = 0.f, p[EE];
            #pragma unroll
            for (int e = 0; e < EE; e++) { p[e] = expf(logit[e] - m); se += p[e]; }
            float inv = 1.f / se;
            float lse = m + logf(se);
            zp += lse * lse;
            int i1 = -1, i2 = -1; float p1 = -1.f, p2 = -1.f;
            #pragma unroll
            for (int e = 0; e < EE; e++) {
                float pe = p[e] * inv;
                pp[e] += pe;
                if (pe > p1)      { p2 = p1; i2 = i1; p1 = pe; i1 = e; }
                else if (pe > p2) { p2 = pe; i2 = e; }
            }
            float s12 = p1 + p2;
            g_sel[2 * t] = i1;  g_sel[2 * t + 1] = i2;
            g_rw[2 * t] = p1 / s12;  g_rw[2 * t + 1] = p2 / s12;
            atomicAdd(&g_counts[i1], 1);
            atomicAdd(&g_counts[i2], 1);
        }
    }
    if (lane == 0) {
        warp_part[warp][0] = zp;
        #pragma unroll
        for (int e = 0; e < EE; e++) warp_part[warp][e + 1] = pp[e];
    }
    __syncthreads();
    if (threadIdx.x == 0) {
        float acc[9];
        #pragma unroll
        for (int j = 0; j < 9; j++) acc[j] = 0.f;
        for (int w = 0; w < 8; w++)
            for (int j = 0; j < 9; j++) acc[j] += warp_part[w][j];
        for (int j = 0; j < 9; j++) g_partials[blockIdx.x][j] = acc[j];
    }
}

// ---------------- finalize: losses, padded offsets, tile->expert map ----------------
__global__ void moe_finalize_kernel(float* __restrict__ d_out) {
    if (threadIdx.x != 0 || blockIdx.x != 0) return;
    float z = 0.f, ps[EE];
    for (int e = 0; e < EE; e++) ps[e] = 0.f;
    for (int b = 0; b < RBLOCKS; b++) {
        z += g_partials[b][0];
        for (int e = 0; e < EE; e++) ps[e] += g_partials[b][e + 1];
    }
    float zl = z / (float)TT;
    float lb = 0.f, fi[EE];
    for (int e = 0; e < EE; e++) {
        fi[e] = (float)g_counts[e] / (float)NN;
        lb += fi[e] * (ps[e] / (float)TT);
    }
    lb *= (float)EE;
    d_out[OUT_OFF + 0] = zl;
    d_out[OUT_OFF + 1] = lb;
    for (int e = 0; e < EE; e++) d_out[OUT_OFF + 2 + e] = fi[e];

    int off = 0;
    for (int e = 0; e < EE; e++) {
        g_offpad[e] = off;
        g_cursor[e] = 0;
        int blocks = (g_counts[e] + 127) >> 7;
        off += blocks << 7;
    }
    int ti = 0;
    for (int e = 0; e < EE; e++) {
        int blocks = (g_counts[e] + 127) >> 7;
        for (int b = 0; b < blocks; b++) g_tile_expert[ti++] = e;
    }
    for (; ti < MAX_TILES; ti++) g_tile_expert[ti] = -1;
}

// ---------------- scatter (token,k) rows into padded per-expert segments ----------------
__global__ void moe_scatter_kernel() {
    int n = blockIdx.x * 256 + threadIdx.x;
    if (n >= NN) return;
    int e = g_sel[n];
    int pos = atomicAdd(&g_cursor[e], 1);
    g_list[g_offpad[e] + pos] = n;
}

// ---------------- GEMM1: H = gelu(gather(x) @ w1_e), 128x128x16 SIMT fp32 ----------------
__global__ __launch_bounds__(256) void moe_gemm1_kernel(
    const float* __restrict__ x, const float* __restrict__ w1)
{
    int by = blockIdx.y, bx = blockIdx.x;
    int e = g_tile_expert[by];
    if (e < 0) return;

    __shared__ float As[2][16][128];
    __shared__ float Bs[2][16][128];
    __shared__ int tok_s[128];

    int tid = threadIdx.x;
    if (tid < 128) {
        int n = g_list[by * 128 + tid];
        tok_s[tid] = (n >= 0) ? (n >> 1) : -1;
    }
    __syncthreads();

    const int ldb = EE * DFF;   // 16384
    const float* Bp = w1 + (size_t)e * DFF + (size_t)bx * 128;

    int a_row = tid >> 1;
    int a_col = (tid & 1) * 8;
    int b_row = tid >> 4;
    int b_col = (tid & 15) * 8;
    int tx = tid & 15, ty = tid >> 4;

    int tokA = tok_s[a_row];
    const float* Ap = (tokA >= 0) ? (x + (size_t)tokA * DD + a_col) : 0;

    float acc[8][8];
    #pragma unroll
    for (int i = 0; i < 8; i++)
        #pragma unroll
        for (int j = 0; j < 8; j++) acc[i][j] = 0.f;

    float pa[8], pb[8];
    // prologue: chunk 0
    if (Ap) {
        float4 v0 = *(const float4*)(Ap + 0);
        float4 v1 = *(const float4*)(Ap + 4);
        pa[0]=v0.x; pa[1]=v0.y; pa[2]=v0.z; pa[3]=v0.w;
        pa[4]=v1.x; pa[5]=v1.y; pa[6]=v1.z; pa[7]=v1.w;
    } else {
        #pragma unroll
        for (int i = 0; i < 8; i++) pa[i] = 0.f;
    }
    {
        const float* bsrc = Bp + (size_t)b_row * ldb + b_col;
        float4 v0 = *(const float4*)(bsrc + 0);
        float4 v1 = *(const float4*)(bsrc + 4);
        pb[0]=v0.x; pb[1]=v0.y; pb[2]=v0.z; pb[3]=v0.w;
        pb[4]=v1.x; pb[5]=v1.y; pb[6]=v1.z; pb[7]=v1.w;
    }
    #pragma unroll
    for (int i = 0; i < 8; i++) As[0][a_col + i][a_row] = pa[i];
    #pragma unroll
    for (int i = 0; i < 8; i++) Bs[0][b_row][b_col + i] = pb[i];
    __syncthreads();

    const int NB = DD / 16;  // 64
    for (int c = 1; c < NB; ++c) {
        int k0 = c * 16;
        if (Ap) {
            float4 v0 = *(const float4*)(Ap + k0 + 0);
            float4 v1 = *(const float4*)(Ap + k0 + 4);
            pa[0]=v0.x; pa[1]=v0.y; pa[2]=v0.z; pa[3]=v0.w;
            pa[4]=v1.x; pa[5]=v1.y; pa[6]=v1.z; pa[7]=v1.w;
        } else {
            #pragma unroll
            for (int i = 0; i < 8; i++) pa[i] = 0.f;
        }
        {
            const float* bsrc = Bp + (size_t)(k0 + b_row) * ldb + b_col;
            float4 v0 = *(const float4*)(bsrc + 0);
            float4 v1 = *(const float4*)(bsrc + 4);
            pb[0]=v0.x; pb[1]=v0.y; pb[2]=v0.z; pb[3]=v0.w;
            pb[4]=v1.x; pb[5]=v1.y; pb[6]=v1.z; pb[7]=v1.w;
        }
        int rb = (c - 1) & 1, wb = c & 1;
        #pragma unroll
        for (int kk = 0; kk < 16; ++kk) {
            float a[8], b[8];
            #pragma unroll
            for (int i = 0; i < 8; i++) a[i] = As[rb][kk][ty * 8 + i];
            #pragma unroll
            for (int j = 0; j < 8; j++) b[j] = Bs[rb][kk][tx * 8 + j];
            #pragma unroll
            for (int i = 0; i < 8; i++)
                #pragma unroll
                for (int j = 0; j < 8; j++)
                    acc[i][j] = fmaf(a[i], b[j], acc[i][j]);
        }
        #pragma unroll
        for (int i = 0; i < 8; i++) As[wb][a_col + i][a_row] = pa[i];
        #pragma unroll
        for (int i = 0; i < 8; i++) Bs[wb][b_row][b_col + i] = pb[i];
        __syncthreads();
    }
    {
        int rb = (NB - 1) & 1;
        #pragma unroll
        for (int kk = 0; kk < 16; ++kk) {
            float a[8], b[8];
            #pragma unroll
            for (int i = 0; i < 8; i++) a[i] = As[rb][kk][ty * 8 + i];
            #pragma unroll
            for (int j = 0; j < 8; j++) b[j] = Bs[rb][kk][tx * 8 + j];
            #pragma unroll
            for (int i = 0; i < 8; i++)
                #pragma unroll
                for (int j = 0; j < 8; j++)
                    acc[i][j] = fmaf(a[i], b[j], acc[i][j]);
        }
    }
    // epilogue: exact-erf gelu, store H at padded position
    size_t hbase = (size_t)(by * 128) * DFF + (size_t)bx * 128;
    #pragma unroll
    for (int i = 0; i < 8; i++) {
        int row = ty * 8 + i;
        float* Hp = g_H + hbase + (size_t)row * DFF + tx * 8;
        float4 o0, o1;
        float g[8];
        #pragma unroll
        for (int j = 0; j < 8; j++) {
            float v = acc[i][j];
            g[j] = 0.5f * v * (1.f + erff(v * 0.70710678118654752f));
        }
        o0.x=g[0]; o0.y=g[1]; o0.z=g[2]; o0.w=g[3];
        o1.x=g[4]; o1.y=g[5]; o1.z=g[6]; o1.w=g[7];
        *(float4*)(Hp + 0) = o0;
        *(float4*)(Hp + 4) = o1;
    }
}

// ---------------- GEMM2: O[n] = (H @ w2_e) * rw[n], scatter by list ----------------
__global__ __launch_bounds__(256) void moe_gemm2_kernel(const float* __restrict__ w2)
{
    int by = blockIdx.y, bx = blockIdx.x;
    int e = g_tile_expert[by];
    if (e < 0) return;

    __shared__ float As[2][16][128];
    __shared__ float Bs[2][16][128];
    __shared__ int   lst_s[128];
    __shared__ float rws_s[128];

    int tid = threadIdx.x;
    if (tid < 128) {
        int n = g_list[by * 128 + tid];
        lst_s[tid] = n;
        rws_s[tid] = (n >= 0) ? g_rw[n] : 0.f;
    }
    __syncthreads();

    const int ldb = DD;  // 1024
    const float* Bp = w2 + (size_t)e * DFF * DD + (size_t)bx * 128;
    const float* Abase = g_H + (size_t)(by * 128) * DFF;

    int a_row = tid >> 1;
    int a_col = (tid & 1) * 8;
    int b_row = tid >> 4;
    int b_col = (tid & 15) * 8;
    int tx = tid & 15, ty = tid >> 4;

    const float* Ap = Abase + (size_t)a_row * DFF + a_col;

    float acc[8][8];
    #pragma unroll
    for (int i = 0; i < 8; i++)
        #pragma unroll
        for (int j = 0; j < 8; j++) acc[i][j] = 0.f;

    float pa[8], pb[8];
    {
        float4 v0 = *(const float4*)(Ap + 0);
        float4 v1 = *(const float4*)(Ap + 4);
        pa[0]=v0.x; pa[1]=v0.y; pa[2]=v0.z; pa[3]=v0.w;
        pa[4]=v1.x; pa[5]=v1.y; pa[6]=v1.z; pa[7]=v1.w;
        const float* bsrc = Bp + (size_t)b_row * ldb + b_col;
        float4 w0 = *(const float4*)(bsrc + 0);
        float4 w1v = *(const float4*)(bsrc + 4);
        pb[0]=w0.x; pb[1]=w0.y; pb[2]=w0.z; pb[3]=w0.w;
        pb[4]=w1v.x; pb[5]=w1v.y; pb[6]=w1v.z; pb[7]=w1v.w;
    }
    #pragma unroll
    for (int i = 0; i < 8; i++) As[0][a_col + i][a_row] = pa[i];
    #pragma unroll
    for (int i = 0; i < 8; i++) Bs[0][b_row][b_col + i] = pb[i];
    __syncthreads();

    const int NB = DFF / 16;  // 128
    for (int c = 1; c < NB; ++c) {
        int k0 = c * 16;
        {
            float4 v0 = *(const float4*)(Ap + k0 + 0);
            float4 v1 = *(const float4*)(Ap + k0 + 4);
            pa[0]=v0.x; pa[1]=v0.y; pa[2]=v0.z; pa[3]=v0.w;
            pa[4]=v1.x; pa[5]=v1.y; pa[6]=v1.z; pa[7]=v1.w;
            const float* bsrc = Bp + (size_t)(k0 + b_row) * ldb + b_col;
            float4 w0 = *(const float4*)(bsrc + 0);
            float4 w1v = *(const float4*)(bsrc + 4);
            pb[0]=w0.x; pb[1]=w0.y; pb[2]=w0.z; pb[3]=w0.w;
            pb[4]=w1v.x; pb[5]=w1v.y; pb[6]=w1v.z; pb[7]=w1v.w;
        }
        int rb = (c - 1) & 1, wb = c & 1;
        #pragma unroll
        for (int kk = 0; kk < 16; ++kk) {
            float a[8], b[8];
            #pragma unroll
            for (int i = 0; i < 8; i++) a[i] = As[rb][kk][ty * 8 + i];
            #pragma unroll
            for (int j = 0; j < 8; j++) b[j] = Bs[rb][kk][tx * 8 + j];
            #pragma unroll
            for (int i = 0; i < 8; i++)
                #pragma unroll
                for (int j = 0; j < 8; j++)
                    acc[i][j] = fmaf(a[i], b[j], acc[i][j]);
        }
        #pragma unroll
        for (int i = 0; i < 8; i++) As[wb][a_col + i][a_row] = pa[i];
        #pragma unroll
        for (int i = 0; i < 8; i++) Bs[wb][b_row][b_col + i] = pb[i];
        __syncthreads();
    }
    {
        int rb = (NB - 1) & 1;
        #pragma unroll
        for (int kk = 0; kk < 16; ++kk) {
            float a[8], b[8];
            #pragma unroll
            for (int i = 0; i < 8; i++) a[i] = As[rb][kk][ty * 8 + i];
            #pragma unroll
            for (int j = 0; j < 8; j++) b[j] = Bs[rb][kk][tx * 8 + j];
            #pragma unroll
            for (int i = 0; i < 8; i++)
                #pragma unroll
                for (int j = 0; j < 8; j++)
                    acc[i][j] = fmaf(a[i], b[j], acc[i][j]);
        }
    }
    // epilogue: weight + scatter to O rows
    #pragma unroll
    for (int i = 0; i < 8; i++) {
        int row = ty * 8 + i;
        int n = lst_s[row];
        if (n < 0) continue;
        float w = rws_s[row];
        float* Op = g_O + (size_t)n * DD + bx * 128 + tx * 8;
        float4 o0, o1;
        o0.x = acc[i][0] * w; o0.y = acc[i][1] * w; o0.z = acc[i][2] * w; o0.w = acc[i][3] * w;
        o1.x = acc[i][4] * w; o1.y = acc[i][5] * w; o1.z = acc[i][6] * w; o1.w = acc[i][7] * w;
        *(float4*)(Op + 0) = o0;
        *(float4*)(Op + 4) = o1;
    }
}

// ---------------- combine: out[t] = O[2t] + O[2t+1] ----------------
__global__ void moe_combine_kernel(float* __restrict__ d_out) {
    int i = blockIdx.x * 256 + threadIdx.x;   // over T*D/4 float4s
    if (i >= TT * DD / 4) return;
    int t = i >> 8;          // D/4 = 256 float4 per token
    int d4 = i & 255;
    const float4* O4 = (const float4*)g_O;
    float4 a = O4[(size_t)(2 * t) * 256 + d4];
    float4 b = O4[(size_t)(2 * t + 1) * 256 + d4];
    float4 o;
    o.x = a.x + b.x; o.y = a.y + b.y; o.z = a.z + b.z; o.w = a.w + b.w;
    ((float4*)d_out)[i] = o;
}

// ---------------- launch ----------------
extern "C" void kernel_launch(void* const* d_in, const int* in_sizes, int n_in,
                              void* d_out, int out_size) {
    const float* x        = (const float*)d_in[0];
    const float* w1       = (const float*)d_in[1];
    const float* w2       = (const float*)d_in[2];
    const float* router_w = (const float*)d_in[3];
    float* out = (float*)d_out;

    moe_init_kernel<<<(MAX_ROWS + 255) / 256, 256>>>();
    moe_router_kernel<<<RBLOCKS, 256>>>(x, router_w);
    moe_finalize_kernel<<<1, 32>>>(out);
    moe_scatter_kernel<<<(NN + 255) / 256, 256>>>();
    moe_gemm1_kernel<<<dim3(DFF / 128, MAX_TILES), 256>>>(x, w1);
    moe_gemm2_kernel<<<dim3(DD / 128, MAX_TILES), 256>>>(w2);
    moe_combine_kernel<<<(TT * DD / 4 + 255) / 256, 256>>>(out);
}

// round 4
// speedup vs baseline: 2.0040x; 2.0040x over previous
#include <cuda_runtime.h>
#include <cuda_bf16.h>
#include <math.h>
#include <stdint.h>

// ---------------- problem constants ----------------
#define TT     16384            // tokens = B*S
#define DD     1024             // n_embd
#define EE     8                // experts
#define DFF    2048             // per-expert ffn width
#define NN     32768            // N = T*K
#define RBLOCKS 128
#define MAX_TILES 264
#define MAX_ROWS (MAX_TILES*128)
#define OUT_OFF ((size_t)TT*DD)

#define STAGES 3
#define STAGE_BYTES 32768       // Ah 8K | Al 8K | Bh 8K | Bl 8K
#define SMEM_BYTES (STAGES*STAGE_BYTES)

// ---------------- device scratch ----------------
__device__ int   g_counts[EE];
__device__ int   g_cursor[EE];
__device__ int   g_offpad[EE];
__device__ int   g_tile_expert[MAX_TILES];
__device__ int   g_sel[NN];
__device__ float g_rw[NN];
__device__ int   g_list[MAX_ROWS];
__device__ float g_partials[RBLOCKS][9];

__device__ __nv_bfloat16 g_zero[DD];                  // stays zero (never written)
__device__ __nv_bfloat16 g_xh[(size_t)TT*DD];
__device__ __nv_bfloat16 g_xl[(size_t)TT*DD];
__device__ __nv_bfloat16 g_w1th[(size_t)EE*DFF*DD];   // [e*DFF+f][d]
__device__ __nv_bfloat16 g_w1tl[(size_t)EE*DFF*DD];
__device__ __nv_bfloat16 g_w2th[(size_t)EE*DD*DFF];   // [e*DD+d][f]
__device__ __nv_bfloat16 g_w2tl[(size_t)EE*DD*DFF];
__device__ __nv_bfloat16 g_Hh[(size_t)MAX_ROWS*DFF];
__device__ __nv_bfloat16 g_Hl[(size_t)MAX_ROWS*DFF];
__device__ float g_O[(size_t)NN*DD];

// ---------------- asm helpers (baseline sm_80+ ISA only) ----------------
__device__ __forceinline__ uint32_t smem_u32(const void* p) {
    uint32_t r;
    asm("{ .reg .u64 t; cvta.to.shared.u64 t, %1; cvt.u32.u64 %0, t; }" : "=r"(r) : "l"(p));
    return r;
}
__device__ __forceinline__ void cp16(uint32_t dst, const void* src) {
    asm volatile("cp.async.cg.shared.global [%0], [%1], 16;" :: "r"(dst), "l"(src) : "memory");
}
#define CP_COMMIT() asm volatile("cp.async.commit_group;" ::: "memory")
#define CP_WAIT0()  asm volatile("cp.async.wait_group 0;" ::: "memory")
#define CP_WAIT1()  asm volatile("cp.async.wait_group 1;" ::: "memory")
#define CP_WAIT2()  asm volatile("cp.async.wait_group 2;" ::: "memory")

__device__ __forceinline__ void ldsm4(uint32_t* r, uint32_t addr) {
    asm volatile("ldmatrix.sync.aligned.m8n8.x4.shared.b16 {%0,%1,%2,%3}, [%4];"
        : "=r"(r[0]), "=r"(r[1]), "=r"(r[2]), "=r"(r[3]) : "r"(addr));
}
__device__ __forceinline__ void mma16816(float* d, const uint32_t* a, const uint32_t* b) {
    asm volatile(
        "mma.sync.aligned.m16n8k16.row.col.f32.bf16.bf16.f32 "
        "{%0,%1,%2,%3}, {%4,%5,%6,%7}, {%8,%9}, {%0,%1,%2,%3};"
        : "+f"(d[0]), "+f"(d[1]), "+f"(d[2]), "+f"(d[3])
        : "r"(a[0]), "r"(a[1]), "r"(a[2]), "r"(a[3]), "r"(b[0]), "r"(b[1]));
}
__device__ __forceinline__ void split_bf16(float v, __nv_bfloat16& hi, __nv_bfloat16& lo) {
    hi = __float2bfloat16_rn(v);
    lo = __float2bfloat16_rn(v - __bfloat162float(hi));
}
// swizzled byte offset inside one 128x32-bf16 smem tile (row stride 64B)
__device__ __forceinline__ uint32_t swz(int row, int c) {
    return (uint32_t)(row * 64 + ((c ^ ((row >> 1) & 3)) * 16));
}

// ---------------- conversion + init kernels ----------------
__global__ __launch_bounds__(256) void conv_x_kernel(const float* __restrict__ x) {
    int i = blockIdx.x * 256 + threadIdx.x;       // over TT*DD/4
    if (i < EE) g_counts[i] = 0;
    if (i < MAX_ROWS) g_list[i] = -1;
    if (i >= TT * DD / 4) return;
    float4 v = ((const float4*)x)[i];
    __nv_bfloat16 h0, h1, h2, h3, l0, l1, l2, l3;
    split_bf16(v.x, h0, l0); split_bf16(v.y, h1, l1);
    split_bf16(v.z, h2, l2); split_bf16(v.w, h3, l3);
    __nv_bfloat162* xh2 = (__nv_bfloat162*)g_xh;
    __nv_bfloat162* xl2 = (__nv_bfloat162*)g_xl;
    xh2[2*i]   = __nv_bfloat162(h0, h1);
    xh2[2*i+1] = __nv_bfloat162(h2, h3);
    xl2[2*i]   = __nv_bfloat162(l0, l1);
    xl2[2*i+1] = __nv_bfloat162(l2, l3);
}

// w1 [D][E*DFF] -> w1t [E*DFF][D] (hi/lo bf16)
__global__ __launch_bounds__(256) void conv_w1_kernel(const float* __restrict__ w1) {
    __shared__ float t[32][33];
    int c0 = blockIdx.x * 32, d0 = blockIdx.y * 32;
    int tx = threadIdx.x, ty = threadIdx.y;           // 32 x 8
    #pragma unroll
    for (int j = 0; j < 32; j += 8)
        t[ty + j][tx] = w1[(size_t)(d0 + ty + j) * (EE * DFF) + c0 + tx];
    __syncthreads();
    #pragma unroll
    for (int j = 0; j < 32; j += 8) {
        float v = t[tx][ty + j];
        __nv_bfloat16 hi, lo; split_bf16(v, hi, lo);
        size_t o = (size_t)(c0 + ty + j) * DD + d0 + tx;
        g_w1th[o] = hi; g_w1tl[o] = lo;
    }
}

// w2 [E*DFF][D] -> w2t [e][d][f] (hi/lo bf16)
__global__ __launch_bounds__(256) void conv_w2_kernel(const float* __restrict__ w2) {
    __shared__ float t[32][33];
    int d0 = blockIdx.x * 32, f0 = blockIdx.y * 32, e = blockIdx.z;
    int tx = threadIdx.x, ty = threadIdx.y;
    #pragma unroll
    for (int j = 0; j < 32; j += 8)
        t[ty + j][tx] = w2[(size_t)(e * DFF + f0 + ty + j) * DD + d0 + tx];
    __syncthreads();
    #pragma unroll
    for (int j = 0; j < 32; j += 8) {
        float v = t[tx][ty + j];
        __nv_bfloat16 hi, lo; split_bf16(v, hi, lo);
        size_t o = (size_t)(e * DD + d0 + ty + j) * DFF + f0 + tx;
        g_w2th[o] = hi; g_w2tl[o] = lo;
    }
}

// ---------------- router ----------------
__global__ __launch_bounds__(256) void moe_router_kernel(
    const float* __restrict__ x, const float* __restrict__ router_w)
{
    __shared__ float rw_s[EE * DD];
    __shared__ float warp_part[8][9];
    for (int i = threadIdx.x; i < EE * DD; i += 256) rw_s[i] = router_w[i];
    __syncthreads();

    int warp = threadIdx.x >> 5, lane = threadIdx.x & 31;
    int wg = blockIdx.x * 8 + warp;
    float zp = 0.f;
    float pp[EE];
    #pragma unroll
    for (int e = 0; e < EE; e++) pp[e] = 0.f;

    for (int t = wg; t < TT; t += RBLOCKS * 8) {
        const float* xr = x + (size_t)t * DD;
        float xv[32];
        #pragma unroll
        for (int i = 0; i < 32; i++) xv[i] = xr[lane + 32 * i];
        float logit[EE];
        #pragma unroll
        for (int e = 0; e < EE; e++) {
            float s = 0.f;
            #pragma unroll
            for (int i = 0; i < 32; i++) s = fmaf(xv[i], rw_s[e * DD + lane + 32 * i], s);
            #pragma unroll
            for (int o = 16; o > 0; o >>= 1) s += __shfl_xor_sync(0xFFFFFFFFu, s, o);
            logit[e] = s;
        }
        if (lane == 0) {
            float m = logit[0];
            #pragma unroll
            for (int e = 1; e < EE; e++) m = fmaxf(m, logit[e]);
            float se = 0.f, p[EE];
            #pragma unroll
            for (int e = 0; e < EE; e++) { p[e] = expf(logit[e] - m); se += p[e]; }
            float inv = 1.f / se;
            float lse = m + logf(se);
            zp += lse * lse;
            int i1 = -1, i2 = -1; float p1 = -1.f, p2 = -1.f;
            #pragma unroll
            for (int e = 0; e < EE; e++) {
                float pe = p[e] * inv;
                pp[e] += pe;
                if (pe > p1)      { p2 = p1; i2 = i1; p1 = pe; i1 = e; }
                else if (pe > p2) { p2 = pe; i2 = e; }
            }
            float s12 = p1 + p2;
            g_sel[2 * t] = i1;  g_sel[2 * t + 1] = i2;
            g_rw[2 * t] = p1 / s12;  g_rw[2 * t + 1] = p2 / s12;
            atomicAdd(&g_counts[i1], 1);
            atomicAdd(&g_counts[i2], 1);
        }
    }
    if (lane == 0) {
        warp_part[warp][0] = zp;
        #pragma unroll
        for (int e = 0; e < EE; e++) warp_part[warp][e + 1] = pp[e];
    }
    __syncthreads();
    if (threadIdx.x == 0) {
        float acc[9];
        #pragma unroll
        for (int j = 0; j < 9; j++) acc[j] = 0.f;
        for (int w = 0; w < 8; w++)
            for (int j = 0; j < 9; j++) acc[j] += warp_part[w][j];
        for (int j = 0; j < 9; j++) g_partials[blockIdx.x][j] = acc[j];
    }
}

__global__ void moe_finalize_kernel(float* __restrict__ d_out) {
    if (threadIdx.x != 0 || blockIdx.x != 0) return;
    float z = 0.f, ps[EE];
    for (int e = 0; e < EE; e++) ps[e] = 0.f;
    for (int b = 0; b < RBLOCKS; b++) {
        z += g_partials[b][0];
        for (int e = 0; e < EE; e++) ps[e] += g_partials[b][e + 1];
    }
    float zl = z / (float)TT;
    float lb = 0.f, fi[EE];
    for (int e = 0; e < EE; e++) {
        fi[e] = (float)g_counts[e] / (float)NN;
        lb += fi[e] * (ps[e] / (float)TT);
    }
    lb *= (float)EE;
    d_out[OUT_OFF + 0] = zl;
    d_out[OUT_OFF + 1] = lb;
    for (int e = 0; e < EE; e++) d_out[OUT_OFF + 2 + e] = fi[e];

    int off = 0;
    for (int e = 0; e < EE; e++) {
        g_offpad[e] = off;
        g_cursor[e] = 0;
        int blocks = (g_counts[e] + 127) >> 7;
        off += blocks << 7;
    }
    int ti = 0;
    for (int e = 0; e < EE; e++) {
        int blocks = (g_counts[e] + 127) >> 7;
        for (int b = 0; b < blocks; b++) g_tile_expert[ti++] = e;
    }
    for (; ti < MAX_TILES; ti++) g_tile_expert[ti] = -1;
}

__global__ void moe_scatter_kernel() {
    int n = blockIdx.x * 256 + threadIdx.x;
    if (n >= NN) return;
    int e = g_sel[n];
    int pos = atomicAdd(&g_cursor[e], 1);
    g_list[g_offpad[e] + pos] = n;
}

// ================= GEMM1: H = gelu(gather(x) @ w1_e^T), mma.sync bf16x3 =================
// tile M=128 N=128, K=1024, slab 32, 3-stage cp.async, 8 warps (4x2), warp = 32x64
__global__ __launch_bounds__(256, 1) void moe_gemm1_mma() {
    extern __shared__ char sm[];
    __shared__ int s_tok[128];

    int by = blockIdx.y, bx = blockIdx.x;
    int e = g_tile_expert[by];
    if (e < 0) return;
    int tid = threadIdx.x;

    if (tid < 128) {
        int n = g_list[by * 128 + tid];
        s_tok[tid] = (n >= 0) ? (n >> 1) : -1;
    }
    __syncthreads();

    uint32_t sb = smem_u32(sm);

    // cp.async geometry: row = tid>>1, two 16B chunks c = (tid&1)*2, +1
    int arow = tid >> 1;
    int ac0 = (tid & 1) * 2;
    uint32_t d0 = swz(arow, ac0), d1 = swz(arow, ac0 + 1);
    int tok = s_tok[arow];
    const __nv_bfloat16* Ah = (tok >= 0) ? g_xh + (size_t)tok * DD : g_zero;
    const __nv_bfloat16* Al = (tok >= 0) ? g_xl + (size_t)tok * DD : g_zero;
    size_t brow = (size_t)(e * DFF + bx * 128 + arow) * DD;
    const __nv_bfloat16* Bh = g_w1th + brow;
    const __nv_bfloat16* Bl = g_w1tl + brow;
    int src0 = ac0 * 8, src1 = ac0 * 8 + 8;

    const int S = DD / 32;   // 32 slabs
    #define G1_LOAD(s) do {                                             \
        uint32_t base = sb + ((s) % STAGES) * STAGE_BYTES;              \
        int k0 = (s) * 32;                                              \
        cp16(base +     0 + d0, Ah + k0 + src0);                        \
        cp16(base +     0 + d1, Ah + k0 + src1);                        \
        cp16(base +  8192 + d0, Al + k0 + src0);                        \
        cp16(base +  8192 + d1, Al + k0 + src1);                        \
        cp16(base + 16384 + d0, Bh + k0 + src0);                        \
        cp16(base + 16384 + d1, Bh + k0 + src1);                        \
        cp16(base + 24576 + d0, Bl + k0 + src0);                        \
        cp16(base + 24576 + d1, Bl + k0 + src1);                        \
        CP_COMMIT();                                                    \
    } while (0)

    int lane = tid & 31, w = tid >> 5;
    int wm = w >> 1, wn = w & 1;

    // ldmatrix geometry
    int rA[2], swA[2];
    #pragma unroll
    for (int mf = 0; mf < 2; mf++) {
        rA[mf] = wm * 32 + mf * 16 + (lane & 15);
        swA[mf] = (rA[mf] >> 1) & 3;
    }
    int kcA = lane >> 4;                       // + kk*2
    int rB[4], swB[4];
    #pragma unroll
    for (int np = 0; np < 4; np++) {
        rB[np] = wn * 64 + np * 16 + (lane & 7) + ((lane >> 4) << 3);
        swB[np] = (rB[np] >> 1) & 3;
    }
    int kcB = (lane >> 3) & 1;                 // + kk*2

    float acc[2][8][4];
    #pragma unroll
    for (int mf = 0; mf < 2; mf++)
        #pragma unroll
        for (int nf = 0; nf < 8; nf++)
            #pragma unroll
            for (int q = 0; q < 4; q++) acc[mf][nf][q] = 0.f;

    G1_LOAD(0); G1_LOAD(1);
    for (int s = 0; s < S; ++s) {
        if (s + 2 < S) { G1_LOAD(s + 2); CP_WAIT2(); }
        else if (s + 1 < S) { CP_WAIT1(); }
        else { CP_WAIT0(); }
        __syncthreads();
        uint32_t base = sb + (s % STAGES) * STAGE_BYTES;
        #pragma unroll
        for (int kk = 0; kk < 2; ++kk) {
            uint32_t ah[2][4], al[2][4], bfr[4][4];
            #pragma unroll
            for (int mf = 0; mf < 2; mf++) {
                uint32_t ao = (uint32_t)(rA[mf] * 64 + (((kk * 2 + kcA) ^ swA[mf]) * 16));
                ldsm4(ah[mf], base + ao);
                ldsm4(al[mf], base + 8192 + ao);
            }
            #pragma unroll
            for (int np = 0; np < 4; np++) {
                uint32_t bo = (uint32_t)(rB[np] * 64 + (((kk * 2 + kcB) ^ swB[np]) * 16));
                ldsm4(bfr[np], base + 16384 + bo);
            }
            #pragma unroll
            for (int mf = 0; mf < 2; mf++)
                #pragma unroll
                for (int np = 0; np < 4; np++) {
                    mma16816(acc[mf][np*2],   ah[mf], &bfr[np][0]);
                    mma16816(acc[mf][np*2+1], ah[mf], &bfr[np][2]);
                    mma16816(acc[mf][np*2],   al[mf], &bfr[np][0]);
                    mma16816(acc[mf][np*2+1], al[mf], &bfr[np][2]);
                }
            #pragma unroll
            for (int np = 0; np < 4; np++) {
                uint32_t bo = (uint32_t)(rB[np] * 64 + (((kk * 2 + kcB) ^ swB[np]) * 16));
                ldsm4(bfr[np], base + 24576 + bo);
            }
            #pragma unroll
            for (int mf = 0; mf < 2; mf++)
                #pragma unroll
                for (int np = 0; np < 4; np++) {
                    mma16816(acc[mf][np*2],   ah[mf], &bfr[np][0]);
                    mma16816(acc[mf][np*2+1], ah[mf], &bfr[np][2]);
                }
        }
        __syncthreads();
    }
    #undef G1_LOAD

    // epilogue: exact gelu + bf16 split
    #pragma unroll
    for (int mf = 0; mf < 2; mf++) {
        int r0 = wm * 32 + mf * 16 + (lane >> 2);
        #pragma unroll
        for (int nf = 0; nf < 8; nf++) {
            int c = wn * 64 + nf * 8 + (lane & 3) * 2;
            size_t base0 = (size_t)(by * 128 + r0) * DFF + bx * 128 + c;
            size_t base1 = (size_t)(by * 128 + r0 + 8) * DFF + bx * 128 + c;
            #pragma unroll
            for (int half = 0; half < 2; half++) {
                float v0 = acc[mf][nf][half * 2], v1 = acc[mf][nf][half * 2 + 1];
                float gl0 = 0.5f * v0 * (1.f + erff(v0 * 0.70710678118654752f));
                float gl1 = 0.5f * v1 * (1.f + erff(v1 * 0.70710678118654752f));
                __nv_bfloat16 h0, l0, h1, l1;
                split_bf16(gl0, h0, l0);
                split_bf16(gl1, h1, l1);
                size_t o = half ? base1 : base0;
                *(__nv_bfloat162*)(g_Hh + o) = __nv_bfloat162(h0, h1);
                *(__nv_bfloat162*)(g_Hl + o) = __nv_bfloat162(l0, l1);
            }
        }
    }
}

// ================= GEMM2: O[n] = (H @ w2_e^T) * rw[n], mma.sync bf16x3 =================
__global__ __launch_bounds__(256, 1) void moe_gemm2_mma() {
    extern __shared__ char sm[];
    __shared__ int   s_n[128];
    __shared__ float s_rw[128];

    int by = blockIdx.y, bx = blockIdx.x;
    int e = g_tile_expert[by];
    if (e < 0) return;
    int tid = threadIdx.x;

    if (tid < 128) {
        int n = g_list[by * 128 + tid];
        s_n[tid] = n;
        s_rw[tid] = (n >= 0) ? g_rw[n] : 0.f;
    }
    __syncthreads();

    uint32_t sb = smem_u32(sm);

    int arow = tid >> 1;
    int ac0 = (tid & 1) * 2;
    uint32_t d0 = swz(arow, ac0), d1 = swz(arow, ac0 + 1);
    size_t harow = (size_t)(by * 128 + arow) * DFF;
    const __nv_bfloat16* Ah = g_Hh + harow;
    const __nv_bfloat16* Al = g_Hl + harow;
    size_t brow = (size_t)(e * DD + bx * 128 + arow) * DFF;
    const __nv_bfloat16* Bh = g_w2th + brow;
    const __nv_bfloat16* Bl = g_w2tl + brow;
    int src0 = ac0 * 8, src1 = ac0 * 8 + 8;

    const int S = DFF / 32;   // 64 slabs
    #define G2_LOAD(s) do {                                             \
        uint32_t base = sb + ((s) % STAGES) * STAGE_BYTES;              \
        int k0 = (s) * 32;                                              \
        cp16(base +     0 + d0, Ah + k0 + src0);                        \
        cp16(base +     0 + d1, Ah + k0 + src1);                        \
        cp16(base +  8192 + d0, Al + k0 + src0);                        \
        cp16(base +  8192 + d1, Al + k0 + src1);                        \
        cp16(base + 16384 + d0, Bh + k0 + src0);                        \
        cp16(base + 16384 + d1, Bh + k0 + src1);                        \
        cp16(base + 24576 + d0, Bl + k0 + src0);                        \
        cp16(base + 24576 + d1, Bl + k0 + src1);                        \
        CP_COMMIT();                                                    \
    } while (0)

    int lane = tid & 31, w = tid >> 5;
    int wm = w >> 1, wn = w & 1;

    int rA[2], swA[2];
    #pragma unroll
    for (int mf = 0; mf < 2; mf++) {
        rA[mf] = wm * 32 + mf * 16 + (lane & 15);
        swA[mf] = (rA[mf] >> 1) & 3;
    }
    int kcA = lane >> 4;
    int rB[4], swB[4];
    #pragma unroll
    for (int np = 0; np < 4; np++) {
        rB[np] = wn * 64 + np * 16 + (lane & 7) + ((lane >> 4) << 3);
        swB[np] = (rB[np] >> 1) & 3;
    }
    int kcB = (lane >> 3) & 1;

    float acc[2][8][4];
    #pragma unroll
    for (int mf = 0; mf < 2; mf++)
        #pragma unroll
        for (int nf = 0; nf < 8; nf++)
            #pragma unroll
            for (int q = 0; q < 4; q++) acc[mf][nf][q] = 0.f;

    G2_LOAD(0); G2_LOAD(1);
    for (int s = 0; s < S; ++s) {
        if (s + 2 < S) { G2_LOAD(s + 2); CP_WAIT2(); }
        else if (s + 1 < S) { CP_WAIT1(); }
        else { CP_WAIT0(); }
        __syncthreads();
        uint32_t base = sb + (s % STAGES) * STAGE_BYTES;
        #pragma unroll
        for (int kk = 0; kk < 2; ++kk) {
            uint32_t ah[2][4], al[2][4], bfr[4][4];
            #pragma unroll
            for (int mf = 0; mf < 2; mf++) {
                uint32_t ao = (uint32_t)(rA[mf] * 64 + (((kk * 2 + kcA) ^ swA[mf]) * 16));
                ldsm4(ah[mf], base + ao);
                ldsm4(al[mf], base + 8192 + ao);
            }
            #pragma unroll
            for (int np = 0; np < 4; np++) {
                uint32_t bo = (uint32_t)(rB[np] * 64 + (((kk * 2 + kcB) ^ swB[np]) * 16));
                ldsm4(bfr[np], base + 16384 + bo);
            }
            #pragma unroll
            for (int mf = 0; mf < 2; mf++)
                #pragma unroll
                for (int np = 0; np < 4; np++) {
                    mma16816(acc[mf][np*2],   ah[mf], &bfr[np][0]);
                    mma16816(acc[mf][np*2+1], ah[mf], &bfr[np][2]);
                    mma16816(acc[mf][np*2],   al[mf], &bfr[np][0]);
                    mma16816(acc[mf][np*2+1], al[mf], &bfr[np][2]);
                }
            #pragma unroll
            for (int np = 0; np < 4; np++) {
                uint32_t bo = (uint32_t)(rB[np] * 64 + (((kk * 2 + kcB) ^ swB[np]) * 16));
                ldsm4(bfr[np], base + 24576 + bo);
            }
            #pragma unroll
            for (int mf = 0; mf < 2; mf++)
                #pragma unroll
                for (int np = 0; np < 4; np++) {
                    mma16816(acc[mf][np*2],   ah[mf], &bfr[np][0]);
                    mma16816(acc[mf][np*2+1], ah[mf], &bfr[np][2]);
                }
        }
        __syncthreads();
    }
    #undef G2_LOAD

    // epilogue: scale by routing weight, scatter into g_O
    #pragma unroll
    for (int mf = 0; mf < 2; mf++) {
        int r0 = wm * 32 + mf * 16 + (lane >> 2);
        int n0 = s_n[r0], n1 = s_n[r0 + 8];
        float w0 = s_rw[r0], w1v = s_rw[r0 + 8];
        #pragma unroll
        for (int nf = 0; nf < 8; nf++) {
            int c = bx * 128 + wn * 64 + nf * 8 + (lane & 3) * 2;
            if (n0 >= 0) {
                float2 o = { acc[mf][nf][0] * w0, acc[mf][nf][1] * w0 };
                *(float2*)(g_O + (size_t)n0 * DD + c) = o;
            }
            if (n1 >= 0) {
                float2 o = { acc[mf][nf][2] * w1v, acc[mf][nf][3] * w1v };
                *(float2*)(g_O + (size_t)n1 * DD + c) = o;
            }
        }
    }
}

// ---------------- combine ----------------
__global__ void moe_combine_kernel(float* __restrict__ d_out) {
    int i = blockIdx.x * 256 + threadIdx.x;
    if (i >= TT * DD / 4) return;
    int t = i >> 8;
    int d4 = i & 255;
    const float4* O4 = (const float4*)g_O;
    float4 a = O4[(size_t)(2 * t) * 256 + d4];
    float4 b = O4[(size_t)(2 * t + 1) * 256 + d4];
    float4 o;
    o.x = a.x + b.x; o.y = a.y + b.y; o.z = a.z + b.z; o.w = a.w + b.w;
    ((float4*)d_out)[i] = o;
}

// ---------------- launch ----------------
extern "C" void kernel_launch(void* const* d_in, const int* in_sizes, int n_in,
                              void* d_out, int out_size) {
    const float* x        = (const float*)d_in[0];
    const float* w1       = (const float*)d_in[1];
    const float* w2       = (const float*)d_in[2];
    const float* router_w = (const float*)d_in[3];
    float* out = (float*)d_out;

    cudaFuncSetAttribute(moe_gemm1_mma, cudaFuncAttributeMaxDynamicSharedMemorySize, SMEM_BYTES);
    cudaFuncSetAttribute(moe_gemm2_mma, cudaFuncAttributeMaxDynamicSharedMemorySize, SMEM_BYTES);

    conv_x_kernel<<<TT * DD / 4 / 256, 256>>>(x);
    conv_w1_kernel<<<dim3(EE * DFF / 32, DD / 32), dim3(32, 8)>>>(w1);
    conv_w2_kernel<<<dim3(DD / 32, DFF / 32, EE), dim3(32, 8)>>>(w2);
    moe_router_kernel<<<RBLOCKS, 256>>>(x, router_w);
    moe_finalize_kernel<<<1, 32>>>(out);
    moe_scatter_kernel<<<(NN + 255) / 256, 256>>>();
    moe_gemm1_mma<<<dim3(DFF / 128, MAX_TILES), 256, SMEM_BYTES>>>();
    moe_gemm2_mma<<<dim3(DD / 128, MAX_TILES), 256, SMEM_BYTES>>>();
    moe_combine_kernel<<<(TT * DD / 4 + 255) / 256, 256>>>(out);
}

// round 9
// speedup vs baseline: 3.8990x; 1.9456x over previous
#include <cuda_runtime.h>
#include <cuda_fp16.h>
#include <math.h>
#include <stdint.h>

// ---------------- problem constants ----------------
#define TT     16384            // tokens = B*S
#define DD     1024             // n_embd
#define EE     8                // experts
#define DFF    2048             // per-expert ffn width
#define NN     32768            // N = T*K
#define RBLOCKS 128
#define MAX_TILES 264
#define MAX_ROWS (MAX_TILES*128)
#define OUT_OFF ((size_t)TT*DD)

#define STAGES 3
#define STAGE_BYTES 16384       // A 8K | B 8K (128 rows x 64B each)
#define SMEM_BYTES (STAGES*STAGE_BYTES)

// ---------------- device scratch (~356 MiB, < R4's 452 MiB which passed) ------------
__device__ int   g_counts[EE];
__device__ int   g_cursor[EE];
__device__ int   g_offpad[EE];
__device__ int   g_tile_expert[MAX_TILES];
__device__ int   g_sel[NN];
__device__ float g_rw[NN];
__device__ int   g_list[MAX_ROWS];
__device__ float g_partials[RBLOCKS][9];

__device__ __half g_zeroh[DD];                        // stays zero (never written)
__device__ __half g_xh[(size_t)TT*DD];                // 32 MiB
__device__ __half g_w1t[(size_t)EE*DFF*DD];           // 32 MiB  [e*DFF+f][d]
__device__ __half g_w2t[(size_t)EE*DD*DFF];           // 32 MiB  [e*DD+d][f]
__device__ __half g_H[(size_t)MAX_ROWS*DFF];          // 132 MiB post-gelu hidden fp16
__device__ float  g_O[(size_t)NN*DD];                 // 128 MiB

// ---------------- asm helpers (baseline sm_80+ ISA only) ----------------
__device__ __forceinline__ uint32_t smem_u32(const void* p) {
    uint32_t r;
    asm("{ .reg .u64 t; cvta.to.shared.u64 t, %1; cvt.u32.u64 %0, t; }" : "=r"(r) : "l"(p));
    return r;
}
__device__ __forceinline__ void cp16(uint32_t dst, const void* src) {
    asm volatile("cp.async.cg.shared.global [%0], [%1], 16;" :: "r"(dst), "l"(src) : "memory");
}
#define CP_COMMIT() asm volatile("cp.async.commit_group;" ::: "memory")
#define CP_WAIT0()  asm volatile("cp.async.wait_group 0;" ::: "memory")
#define CP_WAIT1()  asm volatile("cp.async.wait_group 1;" ::: "memory")
#define CP_WAIT2()  asm volatile("cp.async.wait_group 2;" ::: "memory")

__device__ __forceinline__ void ldsm4(uint32_t* r, uint32_t addr) {
    asm volatile("ldmatrix.sync.aligned.m8n8.x4.shared.b16 {%0,%1,%2,%3}, [%4];"
        : "=r"(r[0]), "=r"(r[1]), "=r"(r[2]), "=r"(r[3]) : "r"(addr));
}
__device__ __forceinline__ void mma16816(float* d, const uint32_t* a, const uint32_t* b) {
    asm volatile(
        "mma.sync.aligned.m16n8k16.row.col.f32.f16.f16.f32 "
        "{%0,%1,%2,%3}, {%4,%5,%6,%7}, {%8,%9}, {%0,%1,%2,%3};"
        : "+f"(d[0]), "+f"(d[1]), "+f"(d[2]), "+f"(d[3])
        : "r"(a[0]), "r"(a[1]), "r"(a[2]), "r"(a[3]), "r"(b[0]), "r"(b[1]));
}
// swizzled byte offset inside one 128x32-fp16 smem tile (row stride 64B)
__device__ __forceinline__ uint32_t swz(int row, int c) {
    return (uint32_t)(row * 64 + ((c ^ ((row >> 1) & 3)) * 16));
}

// ---------------- conversion + init kernels ----------------
__global__ __launch_bounds__(256) void conv_x_kernel(const float* __restrict__ x) {
    int i = blockIdx.x * 256 + threadIdx.x;       // over TT*DD/4
    if (i < EE) g_counts[i] = 0;
    if (i < MAX_ROWS) g_list[i] = -1;
    if (i >= TT * DD / 4) return;
    float4 v = ((const float4*)x)[i];
    __half2* xh2 = (__half2*)g_xh;
    xh2[2*i]   = __floats2half2_rn(v.x, v.y);
    xh2[2*i+1] = __floats2half2_rn(v.z, v.w);
}

// w1 [D][E*DFF] -> w1t [E*DFF][D] fp16
__global__ __launch_bounds__(256) void conv_w1_kernel(const float* __restrict__ w1) {
    __shared__ float t[32][33];
    int c0 = blockIdx.x * 32, d0 = blockIdx.y * 32;
    int tx = threadIdx.x, ty = threadIdx.y;           // 32 x 8
    #pragma unroll
    for (int j = 0; j < 32; j += 8)
        t[ty + j][tx] = w1[(size_t)(d0 + ty + j) * (EE * DFF) + c0 + tx];
    __syncthreads();
    #pragma unroll
    for (int j = 0; j < 32; j += 8)
        g_w1t[(size_t)(c0 + ty + j) * DD + d0 + tx] = __float2half_rn(t[tx][ty + j]);
}

// w2 [E*DFF][D] -> w2t [e][d][f] fp16
__global__ __launch_bounds__(256) void conv_w2_kernel(const float* __restrict__ w2) {
    __shared__ float t[32][33];
    int d0 = blockIdx.x * 32, f0 = blockIdx.y * 32, e = blockIdx.z;
    int tx = threadIdx.x, ty = threadIdx.y;
    #pragma unroll
    for (int j = 0; j < 32; j += 8)
        t[ty + j][tx] = w2[(size_t)(e * DFF + f0 + ty + j) * DD + d0 + tx];
    __syncthreads();
    #pragma unroll
    for (int j = 0; j < 32; j += 8)
        g_w2t[(size_t)(e * DD + d0 + ty + j) * DFF + f0 + tx] = __float2half_rn(t[tx][ty + j]);
}

// ---------------- router ----------------
__global__ __launch_bounds__(256) void moe_router_kernel(
    const float* __restrict__ x, const float* __restrict__ router_w)
{
    __shared__ float rw_s[EE * DD];
    __shared__ float warp_part[8][9];
    for (int i = threadIdx.x; i < EE * DD; i += 256) rw_s[i] = router_w[i];
    __syncthreads();

    int warp = threadIdx.x >> 5, lane = threadIdx.x & 31;
    int wg = blockIdx.x * 8 + warp;
    float zp = 0.f;
    float pp[EE];
    #pragma unroll
    for (int e = 0; e < EE; e++) pp[e] = 0.f;

    for (int t = wg; t < TT; t += RBLOCKS * 8) {
        const float* xr = x + (size_t)t * DD;
        float xv[32];
        #pragma unroll
        for (int i = 0; i < 32; i++) xv[i] = xr[lane + 32 * i];
        float logit[EE];
        #pragma unroll
        for (int e = 0; e < EE; e++) {
            float s = 0.f;
            #pragma unroll
            for (int i = 0; i < 32; i++) s = fmaf(xv[i], rw_s[e * DD + lane + 32 * i], s);
            #pragma unroll
            for (int o = 16; o > 0; o >>= 1) s += __shfl_xor_sync(0xFFFFFFFFu, s, o);
            logit[e] = s;
        }
        if (lane == 0) {
            float m = logit[0];
            #pragma unroll
            for (int e = 1; e < EE; e++) m = fmaxf(m, logit[e]);
            float se = 0.f, p[EE];
            #pragma unroll
            for (int e = 0; e < EE; e++) { p[e] = expf(logit[e] - m); se += p[e]; }
            float inv = 1.f / se;
            float lse = m + logf(se);
            zp += lse * lse;
            int i1 = -1, i2 = -1; float p1 = -1.f, p2 = -1.f;
            #pragma unroll
            for (int e = 0; e < EE; e++) {
                float pe = p[e] * inv;
                pp[e] += pe;
                if (pe > p1)      { p2 = p1; i2 = i1; p1 = pe; i1 = e; }
                else if (pe > p2) { p2 = pe; i2 = e; }
            }
            float s12 = p1 + p2;
            g_sel[2 * t] = i1;  g_sel[2 * t + 1] = i2;
            g_rw[2 * t] = p1 / s12;  g_rw[2 * t + 1] = p2 / s12;
            atomicAdd(&g_counts[i1], 1);
            atomicAdd(&g_counts[i2], 1);
        }
    }
    if (lane == 0) {
        warp_part[warp][0] = zp;
        #pragma unroll
        for (int e = 0; e < EE; e++) warp_part[warp][e + 1] = pp[e];
    }
    __syncthreads();
    if (threadIdx.x == 0) {
        float acc[9];
        #pragma unroll
        for (int j = 0; j < 9; j++) acc[j] = 0.f;
        for (int w = 0; w < 8; w++)
            for (int j = 0; j < 9; j++) acc[j] += warp_part[w][j];
        for (int j = 0; j < 9; j++) g_partials[blockIdx.x][j] = acc[j];
    }
}

__global__ void moe_finalize_kernel(float* __restrict__ d_out) {
    if (threadIdx.x != 0 || blockIdx.x != 0) return;
    float z = 0.f, ps[EE];
    for (int e = 0; e < EE; e++) ps[e] = 0.f;
    for (int b = 0; b < RBLOCKS; b++) {
        z += g_partials[b][0];
        for (int e = 0; e < EE; e++) ps[e] += g_partials[b][e + 1];
    }
    float zl = z / (float)TT;
    float lb = 0.f, fi[EE];
    for (int e = 0; e < EE; e++) {
        fi[e] = (float)g_counts[e] / (float)NN;
        lb += fi[e] * (ps[e] / (float)TT);
    }
    lb *= (float)EE;
    d_out[OUT_OFF + 0] = zl;
    d_out[OUT_OFF + 1] = lb;
    for (int e = 0; e < EE; e++) d_out[OUT_OFF + 2 + e] = fi[e];

    int off = 0;
    for (int e = 0; e < EE; e++) {
        g_offpad[e] = off;
        g_cursor[e] = 0;
        int blocks = (g_counts[e] + 127) >> 7;
        off += blocks << 7;
    }
    int ti = 0;
    for (int e = 0; e < EE; e++) {
        int blocks = (g_counts[e] + 127) >> 7;
        for (int b = 0; b < blocks; b++) g_tile_expert[ti++] = e;
    }
    for (; ti < MAX_TILES; ti++) g_tile_expert[ti] = -1;
}

__global__ void moe_scatter_kernel() {
    int n = blockIdx.x * 256 + threadIdx.x;
    if (n >= NN) return;
    int e = g_sel[n];
    int pos = atomicAdd(&g_cursor[e], 1);
    g_list[g_offpad[e] + pos] = n;
}

// ================= GEMM1: H = gelu(gather(x) @ w1_e^T), mma.sync fp16 x1 ============
// tile M=128 N=128, K=1024, slab 32, 3-stage cp.async, 8 warps (4x2), warp = 32x64
__global__ __launch_bounds__(256, 1) void moe_gemm1_mma() {
    extern __shared__ char sm[];
    __shared__ int s_tok[128];

    int by = blockIdx.y, bx = blockIdx.x;
    int e = g_tile_expert[by];
    if (e < 0) return;
    int tid = threadIdx.x;

    if (tid < 128) {
        int n = g_list[by * 128 + tid];
        s_tok[tid] = (n >= 0) ? (n >> 1) : -1;
    }
    __syncthreads();

    uint32_t sb = smem_u32(sm);

    int arow = tid >> 1;
    int ac0 = (tid & 1) * 2;
    uint32_t d0 = swz(arow, ac0), d1 = swz(arow, ac0 + 1);
    int tok = s_tok[arow];
    const __half* Ah = (tok >= 0) ? g_xh + (size_t)tok * DD : g_zeroh;
    size_t brow = (size_t)(e * DFF + bx * 128 + arow) * DD;
    const __half* Bh = g_w1t + brow;
    int src0 = ac0 * 8, src1 = ac0 * 8 + 8;

    const int S = DD / 32;   // 32 slabs
    #define G1_LOAD(s) do {                                             \
        uint32_t base = sb + ((s) % STAGES) * STAGE_BYTES;              \
        int k0 = (s) * 32;                                              \
        cp16(base +    0 + d0, Ah + k0 + src0);                         \
        cp16(base +    0 + d1, Ah + k0 + src1);                         \
        cp16(base + 8192 + d0, Bh + k0 + src0);                         \
        cp16(base + 8192 + d1, Bh + k0 + src1);                         \
        CP_COMMIT();                                                    \
    } while (0)

    int lane = tid & 31, w = tid >> 5;
    int wm = w >> 1, wn = w & 1;

    int rA[2], swA[2];
    #pragma unroll
    for (int mf = 0; mf < 2; mf++) {
        rA[mf] = wm * 32 + mf * 16 + (lane & 15);
        swA[mf] = (rA[mf] >> 1) & 3;
    }
    int kcA = lane >> 4;                       // + kk*2
    int rB[4], swB[4];
    #pragma unroll
    for (int np = 0; np < 4; np++) {
        rB[np] = wn * 64 + np * 16 + (lane & 7) + ((lane >> 4) << 3);
        swB[np] = (rB[np] >> 1) & 3;
    }
    int kcB = (lane >> 3) & 1;                 // + kk*2

    float acc[2][8][4];
    #pragma unroll
    for (int mf = 0; mf < 2; mf++)
        #pragma unroll
        for (int nf = 0; nf < 8; nf++)
            #pragma unroll
            for (int q = 0; q < 4; q++) acc[mf][nf][q] = 0.f;

    G1_LOAD(0); G1_LOAD(1);
    for (int s = 0; s < S; ++s) {
        if (s + 2 < S) { G1_LOAD(s + 2); CP_WAIT2(); }
        else if (s + 1 < S) { CP_WAIT1(); }
        else { CP_WAIT0(); }
        __syncthreads();
        uint32_t base = sb + (s % STAGES) * STAGE_BYTES;
        #pragma unroll
        for (int kk = 0; kk < 2; ++kk) {
            uint32_t ah[2][4], bfr[4][4];
            #pragma unroll
            for (int mf = 0; mf < 2; mf++) {
                uint32_t ao = (uint32_t)(rA[mf] * 64 + (((kk * 2 + kcA) ^ swA[mf]) * 16));
                ldsm4(ah[mf], base + ao);
            }
            #pragma unroll
            for (int np = 0; np < 4; np++) {
                uint32_t bo = (uint32_t)(rB[np] * 64 + (((kk * 2 + kcB) ^ swB[np]) * 16));
                ldsm4(bfr[np], base + 8192 + bo);
            }
            #pragma unroll
            for (int mf = 0; mf < 2; mf++)
                #pragma unroll
                for (int np = 0; np < 4; np++) {
                    mma16816(acc[mf][np*2],   ah[mf], &bfr[np][0]);
                    mma16816(acc[mf][np*2+1], ah[mf], &bfr[np][2]);
                }
        }
        __syncthreads();
    }
    #undef G1_LOAD

    // epilogue: exact gelu -> fp16 H
    #pragma unroll
    for (int mf = 0; mf < 2; mf++) {
        int r0 = wm * 32 + mf * 16 + (lane >> 2);
        #pragma unroll
        for (int nf = 0; nf < 8; nf++) {
            int c = wn * 64 + nf * 8 + (lane & 3) * 2;
            size_t base0 = (size_t)(by * 128 + r0) * DFF + bx * 128 + c;
            size_t base1 = (size_t)(by * 128 + r0 + 8) * DFF + bx * 128 + c;
            #pragma unroll
            for (int half_ = 0; half_ < 2; half_++) {
                float v0 = acc[mf][nf][half_ * 2], v1 = acc[mf][nf][half_ * 2 + 1];
                float gl0 = 0.5f * v0 * (1.f + erff(v0 * 0.70710678118654752f));
                float gl1 = 0.5f * v1 * (1.f + erff(v1 * 0.70710678118654752f));
                *(__half2*)(g_H + (half_ ? base1 : base0)) = __floats2half2_rn(gl0, gl1);
            }
        }
    }
}

// ================= GEMM2: O[n] = (H @ w2_e^T) * rw[n], mma.sync fp16 x1 =============
__global__ __launch_bounds__(256, 1) void moe_gemm2_mma() {
    extern __shared__ char sm[];
    __shared__ int   s_n[128];
    __shared__ float s_rw[128];

    int by = blockIdx.y, bx = blockIdx.x;
    int e = g_tile_expert[by];
    if (e < 0) return;
    int tid = threadIdx.x;

    if (tid < 128) {
        int n = g_list[by * 128 + tid];
        s_n[tid] = n;
        s_rw[tid] = (n >= 0) ? g_rw[n] : 0.f;
    }
    __syncthreads();

    uint32_t sb = smem_u32(sm);

    int arow = tid >> 1;
    int ac0 = (tid & 1) * 2;
    uint32_t d0 = swz(arow, ac0), d1 = swz(arow, ac0 + 1);
    const __half* Ah = g_H + (size_t)(by * 128 + arow) * DFF;
    size_t brow = (size_t)(e * DD + bx * 128 + arow) * DFF;
    const __half* Bh = g_w2t + brow;
    int src0 = ac0 * 8, src1 = ac0 * 8 + 8;

    const int S = DFF / 32;   // 64 slabs
    #define G2_LOAD(s) do {                                             \
        uint32_t base = sb + ((s) % STAGES) * STAGE_BYTES;              \
        int k0 = (s) * 32;                                              \
        cp16(base +    0 + d0, Ah + k0 + src0);                         \
        cp16(base +    0 + d1, Ah + k0 + src1);                         \
        cp16(base + 8192 + d0, Bh + k0 + src0);                         \
        cp16(base + 8192 + d1, Bh + k0 + src1);                         \
        CP_COMMIT();                                                    \
    } while (0)

    int lane = tid & 31, w = tid >> 5;
    int wm = w >> 1, wn = w & 1;

    int rA[2], swA[2];
    #pragma unroll
    for (int mf = 0; mf < 2; mf++) {
        rA[mf] = wm * 32 + mf * 16 + (lane & 15);
        swA[mf] = (rA[mf] >> 1) & 3;
    }
    int kcA = lane >> 4;
    int rB[4], swB[4];
    #pragma unroll
    for (int np = 0; np < 4; np++) {
        rB[np] = wn * 64 + np * 16 + (lane & 7) + ((lane >> 4) << 3);
        swB[np] = (rB[np] >> 1) & 3;
    }
    int kcB = (lane >> 3) & 1;

    float acc[2][8][4];
    #pragma unroll
    for (int mf = 0; mf < 2; mf++)
        #pragma unroll
        for (int nf = 0; nf < 8; nf++)
            #pragma unroll
            for (int q = 0; q < 4; q++) acc[mf][nf][q] = 0.f;

    G2_LOAD(0); G2_LOAD(1);
    for (int s = 0; s < S; ++s) {
        if (s + 2 < S) { G2_LOAD(s + 2); CP_WAIT2(); }
        else if (s + 1 < S) { CP_WAIT1(); }
        else { CP_WAIT0(); }
        __syncthreads();
        uint32_t base = sb + (s % STAGES) * STAGE_BYTES;
        #pragma unroll
        for (int kk = 0; kk < 2; ++kk) {
            uint32_t ah[2][4], bfr[4][4];
            #pragma unroll
            for (int mf = 0; mf < 2; mf++) {
                uint32_t ao = (uint32_t)(rA[mf] * 64 + (((kk * 2 + kcA) ^ swA[mf]) * 16));
                ldsm4(ah[mf], base + ao);
            }
            #pragma unroll
            for (int np = 0; np < 4; np++) {
                uint32_t bo = (uint32_t)(rB[np] * 64 + (((kk * 2 + kcB) ^ swB[np]) * 16));
                ldsm4(bfr[np], base + 8192 + bo);
            }
            #pragma unroll
            for (int mf = 0; mf < 2; mf++)
                #pragma unroll
                for (int np = 0; np < 4; np++) {
                    mma16816(acc[mf][np*2],   ah[mf], &bfr[np][0]);
                    mma16816(acc[mf][np*2+1], ah[mf], &bfr[np][2]);
                }
        }
        __syncthreads();
    }
    #undef G2_LOAD

    // epilogue: scale by routing weight, scatter into g_O
    #pragma unroll
    for (int mf = 0; mf < 2; mf++) {
        int r0 = wm * 32 + mf * 16 + (lane >> 2);
        int n0 = s_n[r0], n1 = s_n[r0 + 8];
        float w0 = s_rw[r0], w1v = s_rw[r0 + 8];
        #pragma unroll
        for (int nf = 0; nf < 8; nf++) {
            int c = bx * 128 + wn * 64 + nf * 8 + (lane & 3) * 2;
            if (n0 >= 0) {
                float2 o = { acc[mf][nf][0] * w0, acc[mf][nf][1] * w0 };
                *(float2*)(g_O + (size_t)n0 * DD + c) = o;
            }
            if (n1 >= 0) {
                float2 o = { acc[mf][nf][2] * w1v, acc[mf][nf][3] * w1v };
                *(float2*)(g_O + (size_t)n1 * DD + c) = o;
            }
        }
    }
}

// ---------------- combine ----------------
__global__ void moe_combine_kernel(float* __restrict__ d_out) {
    int i = blockIdx.x * 256 + threadIdx.x;
    if (i >= TT * DD / 4) return;
    int t = i >> 8;
    int d4 = i & 255;
    const float4* O4 = (const float4*)g_O;
    float4 a = O4[(size_t)(2 * t) * 256 + d4];
    float4 b = O4[(size_t)(2 * t + 1) * 256 + d4];
    float4 o;
    o.x = a.x + b.x; o.y = a.y + b.y; o.z = a.z + b.z; o.w = a.w + b.w;
    ((float4*)d_out)[i] = o;
}

// ---------------- launch ----------------
extern "C" void kernel_launch(void* const* d_in, const int* in_sizes, int n_in,
                              void* d_out, int out_size) {
    const float* x        = (const float*)d_in[0];
    const float* w1       = (const float*)d_in[1];
    const float* w2       = (const float*)d_in[2];
    const float* router_w = (const float*)d_in[3];
    float* out = (float*)d_out;

    cudaFuncSetAttribute(moe_gemm1_mma, cudaFuncAttributeMaxDynamicSharedMemorySize, SMEM_BYTES);
    cudaFuncSetAttribute(moe_gemm2_mma, cudaFuncAttributeMaxDynamicSharedMemorySize, SMEM_BYTES);

    conv_x_kernel<<<TT * DD / 4 / 256, 256>>>(x);
    conv_w1_kernel<<<dim3(EE * DFF / 32, DD / 32), dim3(32, 8)>>>(w1);
    conv_w2_kernel<<<dim3(DD / 32, DFF / 32, EE), dim3(32, 8)>>>(w2);
    moe_router_kernel<<<RBLOCKS, 256>>>(x, router_w);
    moe_finalize_kernel<<<1, 32>>>(out);
    moe_scatter_kernel<<<(NN + 255) / 256, 256>>>();
    moe_gemm1_mma<<<dim3(DFF / 128, MAX_TILES), 256, SMEM_BYTES>>>();
    moe_gemm2_mma<<<dim3(DD / 128, MAX_TILES), 256, SMEM_BYTES>>>();
    moe_combine_kernel<<<(TT * DD / 4 + 255) / 256, 256>>>(out);
}

// round 10
// speedup vs baseline: 5.4051x; 1.3863x over previous
#include <cuda_runtime.h>
#include <cuda_fp16.h>
#include <math.h>
#include <stdint.h>

// ---------------- problem constants ----------------
#define TT     16384            // tokens = B*S
#define DD     1024             // n_embd
#define EE     8                // experts
#define DFF    2048             // per-expert ffn width
#define NN     32768            // N = T*K
#define RBLOCKS 128
#define MAX_TILES 264
#define MAX_ROWS (MAX_TILES*128)
#define OUT_OFF ((size_t)TT*DD)

#define STAGES 3
#define STAGE_BYTES 16384       // A 8K | B 8K (128 rows x 64B each)
#define SMEM_BYTES (STAGES*STAGE_BYTES)

// ---------------- device scratch (~228 MiB) ----------------
__device__ int   g_counts[EE];
__device__ int   g_cursor[EE];
__device__ int   g_offpad[EE];
__device__ int   g_tile_expert[MAX_TILES];
__device__ int   g_sel[NN];
__device__ float g_rw[NN];
__device__ int   g_list[MAX_ROWS];
__device__ float g_partials[RBLOCKS][9];

__device__ __half g_zeroh[DD];                        // stays zero (never written)
__device__ __half g_xh[(size_t)TT*DD];                // 32 MiB
__device__ __half g_w1t[(size_t)EE*DFF*DD];           // 32 MiB  [e*DFF+f][d]
__device__ __half g_w2t[(size_t)EE*DD*DFF];           // 32 MiB  [e*DD+d][f]
__device__ __half g_H[(size_t)MAX_ROWS*DFF];          // 132 MiB post-gelu hidden fp16

// ---------------- asm helpers (baseline sm_80+ ISA only) ----------------
__device__ __forceinline__ uint32_t smem_u32(const void* p) {
    uint32_t r;
    asm("{ .reg .u64 t; cvta.to.shared.u64 t, %1; cvt.u32.u64 %0, t; }" : "=r"(r) : "l"(p));
    return r;
}
__device__ __forceinline__ void cp16(uint32_t dst, const void* src) {
    asm volatile("cp.async.cg.shared.global [%0], [%1], 16;" :: "r"(dst), "l"(src) : "memory");
}
#define CP_COMMIT() asm volatile("cp.async.commit_group;" ::: "memory")
#define CP_WAIT0()  asm volatile("cp.async.wait_group 0;" ::: "memory")
#define CP_WAIT1()  asm volatile("cp.async.wait_group 1;" ::: "memory")
#define CP_WAIT2()  asm volatile("cp.async.wait_group 2;" ::: "memory")

__device__ __forceinline__ void ldsm4(uint32_t* r, uint32_t addr) {
    asm volatile("ldmatrix.sync.aligned.m8n8.x4.shared.b16 {%0,%1,%2,%3}, [%4];"
        : "=r"(r[0]), "=r"(r[1]), "=r"(r[2]), "=r"(r[3]) : "r"(addr));
}
__device__ __forceinline__ void mma16816(float* d, const uint32_t* a, const uint32_t* b) {
    asm volatile(
        "mma.sync.aligned.m16n8k16.row.col.f32.f16.f16.f32 "
        "{%0,%1,%2,%3}, {%4,%5,%6,%7}, {%8,%9}, {%0,%1,%2,%3};"
        : "+f"(d[0]), "+f"(d[1]), "+f"(d[2]), "+f"(d[3])
        : "r"(a[0]), "r"(a[1]), "r"(a[2]), "r"(a[3]), "r"(b[0]), "r"(b[1]));
}
// swizzled byte offset inside one 128x32-fp16 smem tile (row stride 64B)
__device__ __forceinline__ uint32_t swz(int row, int c) {
    return (uint32_t)(row * 64 + ((c ^ ((row >> 1) & 3)) * 16));
}

// ---------------- conversion + init kernels ----------------
__global__ __launch_bounds__(256) void conv_x_kernel(const float* __restrict__ x,
                                                     float* __restrict__ d_out) {
    int i = blockIdx.x * 256 + threadIdx.x;       // over TT*DD/4
    if (i < EE) g_counts[i] = 0;
    if (i < MAX_ROWS) g_list[i] = -1;
    if (i >= TT * DD / 4) return;
    float4 v = ((const float4*)x)[i];
    __half2* xh2 = (__half2*)g_xh;
    xh2[2*i]   = __floats2half2_rn(v.x, v.y);
    xh2[2*i+1] = __floats2half2_rn(v.z, v.w);
    // zero d_out (GEMM2 accumulates into it atomically)
    ((float4*)d_out)[i] = make_float4(0.f, 0.f, 0.f, 0.f);
}

// w1 [D][E*DFF] -> w1t [E*DFF][D] fp16
__global__ __launch_bounds__(256) void conv_w1_kernel(const float* __restrict__ w1) {
    __shared__ float t[32][33];
    int c0 = blockIdx.x * 32, d0 = blockIdx.y * 32;
    int tx = threadIdx.x, ty = threadIdx.y;           // 32 x 8
    #pragma unroll
    for (int j = 0; j < 32; j += 8)
        t[ty + j][tx] = w1[(size_t)(d0 + ty + j) * (EE * DFF) + c0 + tx];
    __syncthreads();
    #pragma unroll
    for (int j = 0; j < 32; j += 8)
        g_w1t[(size_t)(c0 + ty + j) * DD + d0 + tx] = __float2half_rn(t[tx][ty + j]);
}

// w2 [E*DFF][D] -> w2t [e][d][f] fp16
__global__ __launch_bounds__(256) void conv_w2_kernel(const float* __restrict__ w2) {
    __shared__ float t[32][33];
    int d0 = blockIdx.x * 32, f0 = blockIdx.y * 32, e = blockIdx.z;
    int tx = threadIdx.x, ty = threadIdx.y;
    #pragma unroll
    for (int j = 0; j < 32; j += 8)
        t[ty + j][tx] = w2[(size_t)(e * DFF + f0 + ty + j) * DD + d0 + tx];
    __syncthreads();
    #pragma unroll
    for (int j = 0; j < 32; j += 8)
        g_w2t[(size_t)(e * DD + d0 + ty + j) * DFF + f0 + tx] = __float2half_rn(t[tx][ty + j]);
}

// ---------------- router ----------------
__global__ __launch_bounds__(256) void moe_router_kernel(
    const float* __restrict__ x, const float* __restrict__ router_w)
{
    __shared__ float rw_s[EE * DD];
    __shared__ float warp_part[8][9];
    for (int i = threadIdx.x; i < EE * DD; i += 256) rw_s[i] = router_w[i];
    __syncthreads();

    int warp = threadIdx.x >> 5, lane = threadIdx.x & 31;
    int wg = blockIdx.x * 8 + warp;
    float zp = 0.f;
    float pp[EE];
    #pragma unroll
    for (int e = 0; e < EE; e++) pp[e] = 0.f;

    for (int t = wg; t < TT; t += RBLOCKS * 8) {
        const float* xr = x + (size_t)t * DD;
        float xv[32];
        #pragma unroll
        for (int i = 0; i < 32; i++) xv[i] = xr[lane + 32 * i];
        float logit[EE];
        #pragma unroll
        for (int e = 0; e < EE; e++) {
            float s = 0.f;
            #pragma unroll
            for (int i = 0; i < 32; i++) s = fmaf(xv[i], rw_s[e * DD + lane + 32 * i], s);
            #pragma unroll
            for (int o = 16; o > 0; o >>= 1) s += __shfl_xor_sync(0xFFFFFFFFu, s, o);
            logit[e] = s;
        }
        if (lane == 0) {
            float m = logit[0];
            #pragma unroll
            for (int e = 1; e < EE; e++) m = fmaxf(m, logit[e]);
            float se = 0.f, p[EE];
            #pragma unroll
            for (int e = 0; e < EE; e++) { p[e] = expf(logit[e] - m); se += p[e]; }
            float inv = 1.f / se;
            float lse = m + logf(se);
            zp += lse * lse;
            int i1 = -1, i2 = -1; float p1 = -1.f, p2 = -1.f;
            #pragma unroll
            for (int e = 0; e < EE; e++) {
                float pe = p[e] * inv;
                pp[e] += pe;
                if (pe > p1)      { p2 = p1; i2 = i1; p1 = pe; i1 = e; }
                else if (pe > p2) { p2 = pe; i2 = e; }
            }
            float s12 = p1 + p2;
            g_sel[2 * t] = i1;  g_sel[2 * t + 1] = i2;
            g_rw[2 * t] = p1 / s12;  g_rw[2 * t + 1] = p2 / s12;
            atomicAdd(&g_counts[i1], 1);
            atomicAdd(&g_counts[i2], 1);
        }
    }
    if (lane == 0) {
        warp_part[warp][0] = zp;
        #pragma unroll
        for (int e = 0; e < EE; e++) warp_part[warp][e + 1] = pp[e];
    }
    __syncthreads();
    if (threadIdx.x == 0) {
        float acc[9];
        #pragma unroll
        for (int j = 0; j < 9; j++) acc[j] = 0.f;
        for (int w = 0; w < 8; w++)
            for (int j = 0; j < 9; j++) acc[j] += warp_part[w][j];
        for (int j = 0; j < 9; j++) g_partials[blockIdx.x][j] = acc[j];
    }
}

__global__ void moe_finalize_kernel(float* __restrict__ d_out) {
    if (threadIdx.x != 0 || blockIdx.x != 0) return;
    float z = 0.f, ps[EE];
    for (int e = 0; e < EE; e++) ps[e] = 0.f;
    for (int b = 0; b < RBLOCKS; b++) {
        z += g_partials[b][0];
        for (int e = 0; e < EE; e++) ps[e] += g_partials[b][e + 1];
    }
    float zl = z / (float)TT;
    float lb = 0.f, fi[EE];
    for (int e = 0; e < EE; e++) {
        fi[e] = (float)g_counts[e] / (float)NN;
        lb += fi[e] * (ps[e] / (float)TT);
    }
    lb *= (float)EE;
    d_out[OUT_OFF + 0] = zl;
    d_out[OUT_OFF + 1] = lb;
    for (int e = 0; e < EE; e++) d_out[OUT_OFF + 2 + e] = fi[e];

    int off = 0;
    for (int e = 0; e < EE; e++) {
        g_offpad[e] = off;
        g_cursor[e] = 0;
        int blocks = (g_counts[e] + 127) >> 7;
        off += blocks << 7;
    }
    int ti = 0;
    for (int e = 0; e < EE; e++) {
        int blocks = (g_counts[e] + 127) >> 7;
        for (int b = 0; b < blocks; b++) g_tile_expert[ti++] = e;
    }
    for (; ti < MAX_TILES; ti++) g_tile_expert[ti] = -1;
}

__global__ void moe_scatter_kernel() {
    int n = blockIdx.x * 256 + threadIdx.x;
    if (n >= NN) return;
    int e = g_sel[n];
    int pos = atomicAdd(&g_cursor[e], 1);
    g_list[g_offpad[e] + pos] = n;
}

// ================= GEMM1: H = gelu(gather(x) @ w1_e^T), mma.sync fp16, 2 CTA/SM ====
__global__ __launch_bounds__(256, 2) void moe_gemm1_mma() {
    extern __shared__ char sm[];
    __shared__ int s_tok[128];

    int by = blockIdx.y, bx = blockIdx.x;
    int e = g_tile_expert[by];
    if (e < 0) return;
    int tid = threadIdx.x;

    if (tid < 128) {
        int n = g_list[by * 128 + tid];
        s_tok[tid] = (n >= 0) ? (n >> 1) : -1;
    }
    __syncthreads();

    uint32_t sb = smem_u32(sm);

    int arow = tid >> 1;
    int ac0 = (tid & 1) * 2;
    uint32_t d0 = swz(arow, ac0), d1 = swz(arow, ac0 + 1);
    int tok = s_tok[arow];
    const __half* Ah = (tok >= 0) ? g_xh + (size_t)tok * DD : g_zeroh;
    size_t brow = (size_t)(e * DFF + bx * 128 + arow) * DD;
    const __half* Bh = g_w1t + brow;
    int src0 = ac0 * 8, src1 = ac0 * 8 + 8;

    const int S = DD / 32;   // 32 slabs
    #define G1_LOAD(s) do {                                             \
        uint32_t base = sb + ((s) % STAGES) * STAGE_BYTES;              \
        int k0 = (s) * 32;                                              \
        cp16(base +    0 + d0, Ah + k0 + src0);                         \
        cp16(base +    0 + d1, Ah + k0 + src1);                         \
        cp16(base + 8192 + d0, Bh + k0 + src0);                         \
        cp16(base + 8192 + d1, Bh + k0 + src1);                         \
        CP_COMMIT();                                                    \
    } while (0)

    int lane = tid & 31, w = tid >> 5;
    int wm = w >> 1, wn = w & 1;

    int rA[2], swA[2];
    #pragma unroll
    for (int mf = 0; mf < 2; mf++) {
        rA[mf] = wm * 32 + mf * 16 + (lane & 15);
        swA[mf] = (rA[mf] >> 1) & 3;
    }
    int kcA = lane >> 4;                       // + kk*2
    int rB[4], swB[4];
    #pragma unroll
    for (int np = 0; np < 4; np++) {
        rB[np] = wn * 64 + np * 16 + (lane & 7) + ((lane >> 4) << 3);
        swB[np] = (rB[np] >> 1) & 3;
    }
    int kcB = (lane >> 3) & 1;                 // + kk*2

    float acc[2][8][4];
    #pragma unroll
    for (int mf = 0; mf < 2; mf++)
        #pragma unroll
        for (int nf = 0; nf < 8; nf++)
            #pragma unroll
            for (int q = 0; q < 4; q++) acc[mf][nf][q] = 0.f;

    G1_LOAD(0); G1_LOAD(1);
    for (int s = 0; s < S; ++s) {
        if (s + 2 < S) { G1_LOAD(s + 2); CP_WAIT2(); }
        else if (s + 1 < S) { CP_WAIT1(); }
        else { CP_WAIT0(); }
        __syncthreads();
        uint32_t base = sb + (s % STAGES) * STAGE_BYTES;
        #pragma unroll
        for (int kk = 0; kk < 2; ++kk) {
            uint32_t ah[2][4], bfr[4][4];
            #pragma unroll
            for (int mf = 0; mf < 2; mf++) {
                uint32_t ao = (uint32_t)(rA[mf] * 64 + (((kk * 2 + kcA) ^ swA[mf]) * 16));
                ldsm4(ah[mf], base + ao);
            }
            #pragma unroll
            for (int np = 0; np < 4; np++) {
                uint32_t bo = (uint32_t)(rB[np] * 64 + (((kk * 2 + kcB) ^ swB[np]) * 16));
                ldsm4(bfr[np], base + 8192 + bo);
            }
            #pragma unroll
            for (int mf = 0; mf < 2; mf++)
                #pragma unroll
                for (int np = 0; np < 4; np++) {
                    mma16816(acc[mf][np*2],   ah[mf], &bfr[np][0]);
                    mma16816(acc[mf][np*2+1], ah[mf], &bfr[np][2]);
                }
        }
        __syncthreads();
    }
    #undef G1_LOAD

    // epilogue: exact gelu -> fp16 H
    #pragma unroll
    for (int mf = 0; mf < 2; mf++) {
        int r0 = wm * 32 + mf * 16 + (lane >> 2);
        #pragma unroll
        for (int nf = 0; nf < 8; nf++) {
            int c = wn * 64 + nf * 8 + (lane & 3) * 2;
            size_t base0 = (size_t)(by * 128 + r0) * DFF + bx * 128 + c;
            size_t base1 = (size_t)(by * 128 + r0 + 8) * DFF + bx * 128 + c;
            #pragma unroll
            for (int half_ = 0; half_ < 2; half_++) {
                float v0 = acc[mf][nf][half_ * 2], v1 = acc[mf][nf][half_ * 2 + 1];
                float gl0 = 0.5f * v0 * (1.f + erff(v0 * 0.70710678118654752f));
                float gl1 = 0.5f * v1 * (1.f + erff(v1 * 0.70710678118654752f));
                *(__half2*)(g_H + (half_ ? base1 : base0)) = __floats2half2_rn(gl0, gl1);
            }
        }
    }
}

// ================= GEMM2: d_out[t] += (H @ w2_e^T) * rw[n], atomic combine ==========
__global__ __launch_bounds__(256, 2) void moe_gemm2_mma(float* __restrict__ d_out) {
    extern __shared__ char sm[];
    __shared__ int   s_n[128];
    __shared__ float s_rw[128];

    int by = blockIdx.y, bx = blockIdx.x;
    int e = g_tile_expert[by];
    if (e < 0) return;
    int tid = threadIdx.x;

    if (tid < 128) {
        int n = g_list[by * 128 + tid];
        s_n[tid] = n;
        s_rw[tid] = (n >= 0) ? g_rw[n] : 0.f;
    }
    __syncthreads();

    uint32_t sb = smem_u32(sm);

    int arow = tid >> 1;
    int ac0 = (tid & 1) * 2;
    uint32_t d0 = swz(arow, ac0), d1 = swz(arow, ac0 + 1);
    const __half* Ah = g_H + (size_t)(by * 128 + arow) * DFF;
    size_t brow = (size_t)(e * DD + bx * 128 + arow) * DFF;
    const __half* Bh = g_w2t + brow;
    int src0 = ac0 * 8, src1 = ac0 * 8 + 8;

    const int S = DFF / 32;   // 64 slabs
    #define G2_LOAD(s) do {                                             \
        uint32_t base = sb + ((s) % STAGES) * STAGE_BYTES;              \
        int k0 = (s) * 32;                                              \
        cp16(base +    0 + d0, Ah + k0 + src0);                         \
        cp16(base +    0 + d1, Ah + k0 + src1);                         \
        cp16(base + 8192 + d0, Bh + k0 + src0);                         \
        cp16(base + 8192 + d1, Bh + k0 + src1);                         \
        CP_COMMIT();                                                    \
    } while (0)

    int lane = tid & 31, w = tid >> 5;
    int wm = w >> 1, wn = w & 1;

    int rA[2], swA[2];
    #pragma unroll
    for (int mf = 0; mf < 2; mf++) {
        rA[mf] = wm * 32 + mf * 16 + (lane & 15);
        swA[mf] = (rA[mf] >> 1) & 3;
    }
    int kcA = lane >> 4;
    int rB[4], swB[4];
    #pragma unroll
    for (int np = 0; np < 4; np++) {
        rB[np] = wn * 64 + np * 16 + (lane & 7) + ((lane >> 4) << 3);
        swB[np] = (rB[np] >> 1) & 3;
    }
    int kcB = (lane >> 3) & 1;

    float acc[2][8][4];
    #pragma unroll
    for (int mf = 0; mf < 2; mf++)
        #pragma unroll
        for (int nf = 0; nf < 8; nf++)
            #pragma unroll
            for (int q = 0; q < 4; q++) acc[mf][nf][q] = 0.f;

    G2_LOAD(0); G2_LOAD(1);
    for (int s = 0; s < S; ++s) {
        if (s + 2 < S) { G2_LOAD(s + 2); CP_WAIT2(); }
        else if (s + 1 < S) { CP_WAIT1(); }
        else { CP_WAIT0(); }
        __syncthreads();
        uint32_t base = sb + (s % STAGES) * STAGE_BYTES;
        #pragma unroll
        for (int kk = 0; kk < 2; ++kk) {
            uint32_t ah[2][4], bfr[4][4];
            #pragma unroll
            for (int mf = 0; mf < 2; mf++) {
                uint32_t ao = (uint32_t)(rA[mf] * 64 + (((kk * 2 + kcA) ^ swA[mf]) * 16));
                ldsm4(ah[mf], base + ao);
            }
            #pragma unroll
            for (int np = 0; np < 4; np++) {
                uint32_t bo = (uint32_t)(rB[np] * 64 + (((kk * 2 + kcB) ^ swB[np]) * 16));
                ldsm4(bfr[np], base + 8192 + bo);
            }
            #pragma unroll
            for (int mf = 0; mf < 2; mf++)
                #pragma unroll
                for (int np = 0; np < 4; np++) {
                    mma16816(acc[mf][np*2],   ah[mf], &bfr[np][0]);
                    mma16816(acc[mf][np*2+1], ah[mf], &bfr[np][2]);
                }
        }
        __syncthreads();
    }
    #undef G2_LOAD

    // epilogue: scale by routing weight, atomic-accumulate into d_out[token]
    // (each output element receives exactly 2 adds onto 0 -> order-invariant)
    #pragma unroll
    for (int mf = 0; mf < 2; mf++) {
        int r0 = wm * 32 + mf * 16 + (lane >> 2);
        int n0 = s_n[r0], n1 = s_n[r0 + 8];
        float w0 = s_rw[r0], w1v = s_rw[r0 + 8];
        #pragma unroll
        for (int nf = 0; nf < 8; nf++) {
            int c = bx * 128 + wn * 64 + nf * 8 + (lane & 3) * 2;
            if (n0 >= 0) {
                float* p = d_out + (size_t)(n0 >> 1) * DD + c;
                atomicAdd(p,     acc[mf][nf][0] * w0);
                atomicAdd(p + 1, acc[mf][nf][1] * w0);
            }
            if (n1 >= 0) {
                float* p = d_out + (size_t)(n1 >> 1) * DD + c;
                atomicAdd(p,     acc[mf][nf][2] * w1v);
                atomicAdd(p + 1, acc[mf][nf][3] * w1v);
            }
        }
    }
}

// ---------------- launch ----------------
extern "C" void kernel_launch(void* const* d_in, const int* in_sizes, int n_in,
                              void* d_out, int out_size) {
    const float* x        = (const float*)d_in[0];
    const float* w1       = (const float*)d_in[1];
    const float* w2       = (const float*)d_in[2];
    const float* router_w = (const float*)d_in[3];
    float* out = (float*)d_out;

    cudaFuncSetAttribute(moe_gemm1_mma, cudaFuncAttributeMaxDynamicSharedMemorySize, SMEM_BYTES);
    cudaFuncSetAttribute(moe_gemm2_mma, cudaFuncAttributeMaxDynamicSharedMemorySize, SMEM_BYTES);

    conv_x_kernel<<<TT * DD / 4 / 256, 256>>>(x, out);
    conv_w1_kernel<<<dim3(EE * DFF / 32, DD / 32), dim3(32, 8)>>>(w1);
    conv_w2_kernel<<<dim3(DD / 32, DFF / 32, EE), dim3(32, 8)>>>(w2);
    moe_router_kernel<<<RBLOCKS, 256>>>(x, router_w);
    moe_finalize_kernel<<<1, 32>>>(out);
    moe_scatter_kernel<<<(NN + 255) / 256, 256>>>();
    moe_gemm1_mma<<<dim3(DFF / 128, MAX_TILES), 256, SMEM_BYTES>>>();
    moe_gemm2_mma<<<dim3(DD / 128, MAX_TILES), 256, SMEM_BYTES>>>(out);
}